// round 3
// baseline (speedup 1.0000x reference)
#include <cuda_runtime.h>
#include <cuda_bf16.h>
#include <cstdint>

#define DD 128
#define NPAPER 100000
#define NAUTHOR 50000

// ---------------- scratch (device globals: no allocation allowed) ------------
__device__ float g_sum_c[(size_t)NPAPER * DD];    // cites  -> paper   sums
__device__ float g_sum_w[(size_t)NPAPER * DD];    // writes -> paper   sums
__device__ float g_sum_wb[(size_t)NAUTHOR * DD];  // wb     -> author  sums
__device__ float g_cnt_c[NPAPER];                 // becomes 1/max(cnt,1)
__device__ float g_cnt_w[NPAPER];
__device__ float g_cnt_wb[NAUTHOR];
__device__ float g_hp[(size_t)NPAPER * DD];       // layer-1 paper activations
__device__ float g_ha[(size_t)NAUTHOR * DD];      // layer-1 author activations
__device__ float g_wr1[DD * DD];                  // Wroot1[0]+Wroot1[1]
__device__ float g_wr2[DD * DD];                  // Wroot2[0]+Wroot2[1]

// ---------------- zero ------------------------------------------------------
__global__ void zero_kernel(float4* __restrict__ p, int n4) {
    int i = blockIdx.x * blockDim.x + threadIdx.x;
    int stride = gridDim.x * blockDim.x;
    float4 z = make_float4(0.f, 0.f, 0.f, 0.f);
    for (; i < n4; i += stride) p[i] = z;
}

// ---------------- edge scatter (mean aggregation numerator) -----------------
// One warp per edge. Each lane handles 4 contiguous floats (16B) of the
// 512B feature row; vector RED quarters the atomic issue count.
// NOTE: edge indices are int32 (JAX x64 disabled downcasts the int64 request).
__global__ void scatter_kernel(const float* __restrict__ x,
                               const int* __restrict__ src,
                               const int* __restrict__ dst,
                               float* __restrict__ sum,
                               float* __restrict__ cnt,
                               int E) {
    int gw = (int)((blockIdx.x * (size_t)blockDim.x + threadIdx.x) >> 5);
    int lane = threadIdx.x & 31;
    if (gw >= E) return;
    int s = src[gw];
    int d = dst[gw];
    float4 v = *(const float4*)(x + (size_t)s * DD + lane * 4);
    float* b = sum + (size_t)d * DD + lane * 4;
    asm volatile("red.global.add.v4.f32 [%0], {%1, %2, %3, %4};"
                 :: "l"(b), "f"(v.x), "f"(v.y), "f"(v.z), "f"(v.w)
                 : "memory");
    if (cnt != nullptr && lane == 0) atomicAdd(cnt + d, 1.0f);
}

// ---------------- cnt -> 1/max(cnt,1) in place ------------------------------
__global__ void inv_kernel(float* __restrict__ c, int n) {
    int i = blockIdx.x * blockDim.x + threadIdx.x;
    if (i < n) c[i] = 1.0f / fmaxf(c[i], 1.0f);
}

// ---------------- small elementwise add (Wroot combine) ---------------------
__global__ void wsum_kernel(const float* __restrict__ a,
                            const float* __restrict__ b,
                            float* __restrict__ o, int n) {
    int i = blockIdx.x * blockDim.x + threadIdx.x;
    if (i < n) o[i] = a[i] + b[i];
}

// ---------------- fused 3-term SAGE GEMM ------------------------------------
// out[m, :] = sum_t (scale_t(m) * A_t[m, :]) @ W_t  + bias0 + bias1, opt relu
// Terms: (A0 * I0) @ W0  +  (A1 * I1) @ W1  +  Ar @ Wr    (A1 may be null)
// BM=64 rows/block, full N=128, BK=32. 256 threads, 4x8 register tile each.
#define BM 64
#define BK 32

__global__ __launch_bounds__(256, 4) void sage_gemm(
    float* __restrict__ out,
    const float* __restrict__ A0, const float* __restrict__ I0, const float* __restrict__ W0,
    const float* __restrict__ A1, const float* __restrict__ I1, const float* __restrict__ W1,
    const float* __restrict__ Ar, const float* __restrict__ Wr,
    const float* __restrict__ bias0, const float* __restrict__ bias1,
    int M, int do_relu)
{
    __shared__ float As[BK][BM + 1];   // +1 pad: conflict-free transposed stores
    __shared__ float Ws[BK][DD];

    const int tid = threadIdx.x;
    const int tx = tid & 15;          // output-col group (8 cols)
    const int ty = tid >> 4;          // output-row group (4 rows)
    const int row0 = blockIdx.x * BM;

    float acc[4][8];
#pragma unroll
    for (int r = 0; r < 4; ++r)
#pragma unroll
        for (int c = 0; c < 8; ++c) acc[r][c] = 0.f;

    const float* Aarr[3] = {A0, A1, Ar};
    const float* Iarr[3] = {I0, I1, nullptr};
    const float* Warr[3] = {W0, W1, Wr};

    for (int t = 0; t < 3; ++t) {
        const float* A = Aarr[t];
        if (A == nullptr) continue;
        const float* I = Iarr[t];
        const float* W = Warr[t];

        for (int k0 = 0; k0 < DD; k0 += BK) {
            // --- load A tile: 64 rows x 32 k -> 512 float4, 2 per thread ---
#pragma unroll
            for (int i = 0; i < 2; ++i) {
                int idx = tid + i * 256;
                int r   = idx >> 3;       // 0..63 row in tile
                int c4  = idx & 7;        // float4 index within 32 k
                int gr  = row0 + r;
                float4 v = make_float4(0.f, 0.f, 0.f, 0.f);
                float s = 1.0f;
                if (gr < M) {
                    v = *(const float4*)(A + (size_t)gr * DD + k0 + c4 * 4);
                    if (I != nullptr) s = I[gr];
                }
                As[c4 * 4 + 0][r] = v.x * s;
                As[c4 * 4 + 1][r] = v.y * s;
                As[c4 * 4 + 2][r] = v.z * s;
                As[c4 * 4 + 3][r] = v.w * s;
            }
            // --- load W tile: 32 k x 128 n -> 1024 float4, 4 per thread ----
#pragma unroll
            for (int i = 0; i < 4; ++i) {
                int idx = tid + i * 256;
                int kr  = idx >> 5;       // 0..31
                int c4  = idx & 31;       // float4 col index
                *(float4*)&Ws[kr][c4 * 4] =
                    *(const float4*)(W + (size_t)(k0 + kr) * DD + c4 * 4);
            }
            __syncthreads();

#pragma unroll
            for (int k = 0; k < BK; ++k) {
                float av[4];
#pragma unroll
                for (int r = 0; r < 4; ++r) av[r] = As[k][ty * 4 + r];
                float4 w0 = *(float4*)&Ws[k][tx * 8];
                float4 w1 = *(float4*)&Ws[k][tx * 8 + 4];
                float wv[8] = {w0.x, w0.y, w0.z, w0.w, w1.x, w1.y, w1.z, w1.w};
#pragma unroll
                for (int r = 0; r < 4; ++r)
#pragma unroll
                    for (int c = 0; c < 8; ++c) acc[r][c] += av[r] * wv[c];
            }
            __syncthreads();
        }
    }

    // --- epilogue: bias + optional relu, float4 stores ----------------------
    float bv[8];
#pragma unroll
    for (int c = 0; c < 8; ++c) {
        int col = tx * 8 + c;
        float b = (bias0 != nullptr) ? bias0[col] : 0.f;
        if (bias1 != nullptr) b += bias1[col];
        bv[c] = b;
    }
#pragma unroll
    for (int r = 0; r < 4; ++r) {
        int gr = row0 + ty * 4 + r;
        if (gr >= M) continue;
        float o[8];
#pragma unroll
        for (int c = 0; c < 8; ++c) {
            float v = acc[r][c] + bv[c];
            if (do_relu) v = fmaxf(v, 0.f);
            o[c] = v;
        }
        *(float4*)&out[(size_t)gr * DD + tx * 8]     = make_float4(o[0], o[1], o[2], o[3]);
        *(float4*)&out[(size_t)gr * DD + tx * 8 + 4] = make_float4(o[4], o[5], o[6], o[7]);
    }
}

// ---------------- launch ----------------------------------------------------
static inline int ceil_div(long long a, int b) { return (int)((a + b - 1) / b); }

extern "C" void kernel_launch(void* const* d_in, const int* in_sizes, int n_in,
                              void* d_out, int out_size)
{
    const float* xp  = (const float*)d_in[0];
    const float* xa  = (const float*)d_in[1];
    const float* Wm1 = (const float*)d_in[2];
    const float* b1  = (const float*)d_in[3];
    const float* Wr1 = (const float*)d_in[4];
    const float* Wm2 = (const float*)d_in[5];
    const float* b2  = (const float*)d_in[6];
    const float* Wr2 = (const float*)d_in[7];
    const int* cs = (const int*)d_in[8];     // edge indices are int32
    const int* cd = (const int*)d_in[9];
    const int* ws = (const int*)d_in[10];
    const int* wd = (const int*)d_in[11];
    const int* bs = (const int*)d_in[12];
    const int* bd = (const int*)d_in[13];
    const int Ec = in_sizes[8];
    const int Ew = in_sizes[10];
    const int Eb = in_sizes[12];

    float *sum_c, *sum_w, *sum_wb, *cnt_c, *cnt_w, *cnt_wb, *hp, *ha, *wr1, *wr2;
    cudaGetSymbolAddress((void**)&sum_c,  g_sum_c);
    cudaGetSymbolAddress((void**)&sum_w,  g_sum_w);
    cudaGetSymbolAddress((void**)&sum_wb, g_sum_wb);
    cudaGetSymbolAddress((void**)&cnt_c,  g_cnt_c);
    cudaGetSymbolAddress((void**)&cnt_w,  g_cnt_w);
    cudaGetSymbolAddress((void**)&cnt_wb, g_cnt_wb);
    cudaGetSymbolAddress((void**)&hp,     g_hp);
    cudaGetSymbolAddress((void**)&ha,     g_ha);
    cudaGetSymbolAddress((void**)&wr1,    g_wr1);
    cudaGetSymbolAddress((void**)&wr2,    g_wr2);

    float* out_p = (float*)d_out;
    float* out_a = out_p + (size_t)NPAPER * DD;

    const int ZB = 1024, ZT = 256;

    // ---- layer 1: zero sums + counts ----
    zero_kernel<<<ZB, ZT>>>((float4*)sum_c,  NPAPER * DD / 4);
    zero_kernel<<<ZB, ZT>>>((float4*)sum_w,  NPAPER * DD / 4);
    zero_kernel<<<ZB, ZT>>>((float4*)sum_wb, NAUTHOR * DD / 4);
    zero_kernel<<<8, ZT>>>((float4*)cnt_c,  NPAPER / 4);
    zero_kernel<<<8, ZT>>>((float4*)cnt_w,  NPAPER / 4);
    zero_kernel<<<8, ZT>>>((float4*)cnt_wb, NAUTHOR / 4);

    // ---- layer 1: scatter ----
    scatter_kernel<<<ceil_div((long long)Ec * 32, 256), 256>>>(xp, cs, cd, sum_c, cnt_c, Ec);
    scatter_kernel<<<ceil_div((long long)Ew * 32, 256), 256>>>(xa, ws, wd, sum_w, cnt_w, Ew);
    scatter_kernel<<<ceil_div((long long)Eb * 32, 256), 256>>>(xp, bs, bd, sum_wb, cnt_wb, Eb);

    // counts depend only on topology -> shared by both layers
    inv_kernel<<<ceil_div(NPAPER, 256), 256>>>(cnt_c, NPAPER);
    inv_kernel<<<ceil_div(NPAPER, 256), 256>>>(cnt_w, NPAPER);
    inv_kernel<<<ceil_div(NAUTHOR, 256), 256>>>(cnt_wb, NAUTHOR);

    // combined root weights (paper dst receives Wroot[0] + Wroot[1] on same x)
    wsum_kernel<<<64, 256>>>(Wr1, Wr1 + DD * DD, wr1, DD * DD);
    wsum_kernel<<<64, 256>>>(Wr2, Wr2 + DD * DD, wr2, DD * DD);

    // ---- layer 1: fused GEMMs (+bias, +relu) ----
    sage_gemm<<<ceil_div(NPAPER, BM), 256>>>(
        hp,
        sum_c, cnt_c, Wm1,                      // cites mean @ Wmsg1[0]
        sum_w, cnt_w, Wm1 + DD * DD,            // writes mean @ Wmsg1[1]
        xp, wr1,                                // xp @ (Wroot1[0]+Wroot1[1])
        b1, b1 + DD, NPAPER, 1);
    sage_gemm<<<ceil_div(NAUTHOR, BM), 256>>>(
        ha,
        sum_wb, cnt_wb, Wm1 + 2 * DD * DD,      // wb mean @ Wmsg1[2]
        nullptr, nullptr, nullptr,
        xa, Wr1 + 2 * DD * DD,                  // xa @ Wroot1[2]
        b1 + 2 * DD, nullptr, NAUTHOR, 1);

    // ---- layer 2: zero sums only (counts reused) ----
    zero_kernel<<<ZB, ZT>>>((float4*)sum_c,  NPAPER * DD / 4);
    zero_kernel<<<ZB, ZT>>>((float4*)sum_w,  NPAPER * DD / 4);
    zero_kernel<<<ZB, ZT>>>((float4*)sum_wb, NAUTHOR * DD / 4);

    // ---- layer 2: scatter on hidden activations ----
    scatter_kernel<<<ceil_div((long long)Ec * 32, 256), 256>>>(hp, cs, cd, sum_c, nullptr, Ec);
    scatter_kernel<<<ceil_div((long long)Ew * 32, 256), 256>>>(ha, ws, wd, sum_w, nullptr, Ew);
    scatter_kernel<<<ceil_div((long long)Eb * 32, 256), 256>>>(hp, bs, bd, sum_wb, nullptr, Eb);

    // ---- layer 2: fused GEMMs straight into d_out ----
    sage_gemm<<<ceil_div(NPAPER, BM), 256>>>(
        out_p,
        sum_c, cnt_c, Wm2,
        sum_w, cnt_w, Wm2 + DD * DD,
        hp, wr2,
        b2, b2 + DD, NPAPER, 0);
    sage_gemm<<<ceil_div(NAUTHOR, BM), 256>>>(
        out_a,
        sum_wb, cnt_wb, Wm2 + 2 * DD * DD,
        nullptr, nullptr, nullptr,
        ha, Wr2 + 2 * DD * DD,
        b2 + 2 * DD, nullptr, NAUTHOR, 0);
}

// round 5
// speedup vs baseline: 1.3358x; 1.3358x over previous
#include <cuda_runtime.h>
#include <cuda_bf16.h>
#include <cstdint>

#define DD 128
#define NPAPER 100000
#define NAUTHOR 50000

// ---------------- scratch (device globals: no allocation allowed) ------------
__device__ float g_sum_c[(size_t)NPAPER * DD];
__device__ float g_sum_w[(size_t)NPAPER * DD];
__device__ float g_sum_wb[(size_t)NAUTHOR * DD];
__device__ float g_cnt_c[NPAPER];
__device__ float g_cnt_w[NPAPER];
__device__ float g_cnt_wb[NAUTHOR];
__device__ float g_hp[(size_t)NPAPER * DD];
__device__ float g_ha[(size_t)NAUTHOR * DD];
__device__ float g_wr1[DD * DD];
__device__ float g_wr2[DD * DD];

__device__ __forceinline__ uint32_t f2tf32(float x) {
    uint32_t u;
    asm("cvt.rna.tf32.f32 %0, %1;" : "=r"(u) : "f"(x));
    return u;
}

// ---------------- zero ------------------------------------------------------
__global__ void zero_kernel(float4* __restrict__ p, int n4) {
    int i = blockIdx.x * blockDim.x + threadIdx.x;
    int stride = gridDim.x * blockDim.x;
    float4 z = make_float4(0.f, 0.f, 0.f, 0.f);
    for (; i < n4; i += stride) p[i] = z;
}

// ---------------- edge scatter ----------------------------------------------
__global__ void scatter_kernel(const float* __restrict__ x,
                               const int* __restrict__ src,
                               const int* __restrict__ dst,
                               float* __restrict__ sum,
                               float* __restrict__ cnt,
                               int E) {
    int gw = (int)((blockIdx.x * (size_t)blockDim.x + threadIdx.x) >> 5);
    int lane = threadIdx.x & 31;
    if (gw >= E) return;
    int s = src[gw];
    int d = dst[gw];
    float4 v = *(const float4*)(x + (size_t)s * DD + lane * 4);
    float* b = sum + (size_t)d * DD + lane * 4;
    asm volatile("red.global.add.v4.f32 [%0], {%1, %2, %3, %4};"
                 :: "l"(b), "f"(v.x), "f"(v.y), "f"(v.z), "f"(v.w) : "memory");
    if (cnt != nullptr && lane == 0) atomicAdd(cnt + d, 1.0f);
}

__global__ void inv_kernel(float* __restrict__ c, int n) {
    int i = blockIdx.x * blockDim.x + threadIdx.x;
    if (i < n) c[i] = 1.0f / fmaxf(c[i], 1.0f);
}

__global__ void wsum_kernel(const float* __restrict__ a,
                            const float* __restrict__ b,
                            float* __restrict__ o, int n) {
    int i = blockIdx.x * blockDim.x + threadIdx.x;
    if (i < n) o[i] = a[i] + b[i];
}

// ---------------- tf32 mma.sync fused 3-term SAGE GEMM -----------------------
// out[m,:] = sum_t (I_t(m) * A_t[m,:]) @ W_t + bias0 + bias1, optional relu.
// CTA: 128x128 output tile, 8 warps (4 row x 2 col), warp tile 32x64.
// mma.sync.m16n8k8 tf32: warp = 2 m-atoms x 8 n-atoms, K in 16 steps of 8.
#define A_STRIDE 132   // words; A-frag LDS bank = (4*group+tig)%32 -> conflict-free
#define W_STRIDE 136   // words; B-frag LDS bank = (8*tig+group)%32 -> conflict-free
#define SMEM_TOTAL (128 * A_STRIDE * 4 + 128 * W_STRIDE * 4)

__global__ __launch_bounds__(256, 1)
void sage_gemm_mma(
    float* __restrict__ out,
    const float* __restrict__ A0, const float* __restrict__ I0, const float* __restrict__ W0,
    const float* __restrict__ A1, const float* __restrict__ I1, const float* __restrict__ W1,
    const float* __restrict__ Ar, const float* __restrict__ Wr,
    const float* __restrict__ bias0, const float* __restrict__ bias1,
    int M, int do_relu)
{
    extern __shared__ uint32_t smem[];
    uint32_t* Asm = smem;                       // [128][A_STRIDE]
    uint32_t* Wsm = smem + 128 * A_STRIDE;      // [128][W_STRIDE]

    const int tid = threadIdx.x;
    const int wid = tid >> 5;
    const int lane = tid & 31;
    const int group = lane >> 2;     // 0..7
    const int tig = lane & 3;        // 0..3
    const int wr = (wid & 3) * 32;   // warp row base in tile
    const int wc = (wid >> 2) * 64;  // warp col base
    const int row0 = blockIdx.x * 128;

    float acc[2][8][4];
#pragma unroll
    for (int am = 0; am < 2; ++am)
#pragma unroll
        for (int nb = 0; nb < 8; ++nb)
#pragma unroll
            for (int j = 0; j < 4; ++j) acc[am][nb][j] = 0.f;

    const float* Aarr[3] = {A0, A1, Ar};
    const float* Iarr[3] = {I0, I1, nullptr};
    const float* Warr[3] = {W0, W1, Wr};

    for (int t = 0; t < 3; ++t) {
        const float* A = Aarr[t];
        if (A == nullptr) continue;
        const float* I = Iarr[t];
        const float* W = Warr[t];

        // --- stage A tile (scaled, tf32) : 128x128, 16 float4/thread --------
#pragma unroll
        for (int i = 0; i < 16; ++i) {
            int idx = tid + i * 256;
            int r = idx >> 5;
            int k4 = idx & 31;
            int gr = row0 + r;
            uint4 u = make_uint4(0u, 0u, 0u, 0u);
            if (gr < M) {
                float4 v = *(const float4*)(A + (size_t)gr * DD + k4 * 4);
                float s = (I != nullptr) ? I[gr] : 1.0f;
                u.x = f2tf32(v.x * s); u.y = f2tf32(v.y * s);
                u.z = f2tf32(v.z * s); u.w = f2tf32(v.w * s);
            }
            *(uint4*)&Asm[r * A_STRIDE + k4 * 4] = u;
        }
        // --- stage W tile (tf32), row-major [k][n] --------------------------
#pragma unroll
        for (int i = 0; i < 16; ++i) {
            int idx = tid + i * 256;
            int k = idx >> 5;
            int n4 = idx & 31;
            float4 w = *(const float4*)(W + (size_t)k * DD + n4 * 4);
            uint4 u;
            u.x = f2tf32(w.x); u.y = f2tf32(w.y);
            u.z = f2tf32(w.z); u.w = f2tf32(w.w);
            *(uint4*)&Wsm[k * W_STRIDE + n4 * 4] = u;
        }
        __syncthreads();

        // --- compute --------------------------------------------------------
#pragma unroll 4
        for (int k0 = 0; k0 < DD; k0 += 8) {
            uint32_t a[2][4];
#pragma unroll
            for (int am = 0; am < 2; ++am) {
                int rb = wr + am * 16;
                a[am][0] = Asm[(rb + group) * A_STRIDE + k0 + tig];
                a[am][1] = Asm[(rb + group + 8) * A_STRIDE + k0 + tig];
                a[am][2] = Asm[(rb + group) * A_STRIDE + k0 + tig + 4];
                a[am][3] = Asm[(rb + group + 8) * A_STRIDE + k0 + tig + 4];
            }
#pragma unroll
            for (int nb = 0; nb < 8; ++nb) {
                uint32_t b0 = Wsm[(k0 + tig) * W_STRIDE + wc + nb * 8 + group];
                uint32_t b1 = Wsm[(k0 + tig + 4) * W_STRIDE + wc + nb * 8 + group];
#pragma unroll
                for (int am = 0; am < 2; ++am) {
                    asm volatile(
                        "mma.sync.aligned.m16n8k8.row.col.f32.tf32.tf32.f32 "
                        "{%0,%1,%2,%3}, {%4,%5,%6,%7}, {%8,%9}, {%0,%1,%2,%3};"
                        : "+f"(acc[am][nb][0]), "+f"(acc[am][nb][1]),
                          "+f"(acc[am][nb][2]), "+f"(acc[am][nb][3])
                        : "r"(a[am][0]), "r"(a[am][1]), "r"(a[am][2]), "r"(a[am][3]),
                          "r"(b0), "r"(b1));
                }
            }
        }
        __syncthreads();
    }

    // --- epilogue: bias + relu, st.global.v2 per (c0,c1)/(c2,c3) pair -------
#pragma unroll
    for (int nb = 0; nb < 8; ++nb) {
        int col = wc + nb * 8 + 2 * tig;
        float bA = 0.f, bB = 0.f;
        if (bias0 != nullptr) { bA = bias0[col]; bB = bias0[col + 1]; }
        if (bias1 != nullptr) { bA += bias1[col]; bB += bias1[col + 1]; }
#pragma unroll
        for (int am = 0; am < 2; ++am) {
            int r_lo = row0 + wr + am * 16 + group;
            int r_hi = r_lo + 8;
            float v0 = acc[am][nb][0] + bA, v1 = acc[am][nb][1] + bB;
            float v2 = acc[am][nb][2] + bA, v3 = acc[am][nb][3] + bB;
            if (do_relu) {
                v0 = fmaxf(v0, 0.f); v1 = fmaxf(v1, 0.f);
                v2 = fmaxf(v2, 0.f); v3 = fmaxf(v3, 0.f);
            }
            if (r_lo < M) *(float2*)&out[(size_t)r_lo * DD + col] = make_float2(v0, v1);
            if (r_hi < M) *(float2*)&out[(size_t)r_hi * DD + col] = make_float2(v2, v3);
        }
    }
}

// ---------------- launch ----------------------------------------------------
static inline int ceil_div(long long a, int b) { return (int)((a + b - 1) / b); }

extern "C" void kernel_launch(void* const* d_in, const int* in_sizes, int n_in,
                              void* d_out, int out_size)
{
    const float* xp  = (const float*)d_in[0];
    const float* xa  = (const float*)d_in[1];
    const float* Wm1 = (const float*)d_in[2];
    const float* b1  = (const float*)d_in[3];
    const float* Wr1 = (const float*)d_in[4];
    const float* Wm2 = (const float*)d_in[5];
    const float* b2  = (const float*)d_in[6];
    const float* Wr2 = (const float*)d_in[7];
    const int* cs = (const int*)d_in[8];
    const int* cd = (const int*)d_in[9];
    const int* ws = (const int*)d_in[10];
    const int* wd = (const int*)d_in[11];
    const int* bs = (const int*)d_in[12];
    const int* bd = (const int*)d_in[13];
    const int Ec = in_sizes[8];
    const int Ew = in_sizes[10];
    const int Eb = in_sizes[12];

    float *sum_c, *sum_w, *sum_wb, *cnt_c, *cnt_w, *cnt_wb, *hp, *ha, *wr1, *wr2;
    cudaGetSymbolAddress((void**)&sum_c,  g_sum_c);
    cudaGetSymbolAddress((void**)&sum_w,  g_sum_w);
    cudaGetSymbolAddress((void**)&sum_wb, g_sum_wb);
    cudaGetSymbolAddress((void**)&cnt_c,  g_cnt_c);
    cudaGetSymbolAddress((void**)&cnt_w,  g_cnt_w);
    cudaGetSymbolAddress((void**)&cnt_wb, g_cnt_wb);
    cudaGetSymbolAddress((void**)&hp,     g_hp);
    cudaGetSymbolAddress((void**)&ha,     g_ha);
    cudaGetSymbolAddress((void**)&wr1,    g_wr1);
    cudaGetSymbolAddress((void**)&wr2,    g_wr2);

    cudaFuncSetAttribute(sage_gemm_mma, cudaFuncAttributeMaxDynamicSharedMemorySize, SMEM_TOTAL);

    float* out_p = (float*)d_out;
    float* out_a = out_p + (size_t)NPAPER * DD;

    const int ZB = 1024, ZT = 256;
    const int GP = ceil_div(NPAPER, 128);   // 782
    const int GA = ceil_div(NAUTHOR, 128);  // 391

    // ---- layer 1: zero sums + counts ----
    zero_kernel<<<ZB, ZT>>>((float4*)sum_c,  NPAPER * DD / 4);
    zero_kernel<<<ZB, ZT>>>((float4*)sum_w,  NPAPER * DD / 4);
    zero_kernel<<<ZB, ZT>>>((float4*)sum_wb, NAUTHOR * DD / 4);
    zero_kernel<<<8, ZT>>>((float4*)cnt_c,  NPAPER / 4);
    zero_kernel<<<8, ZT>>>((float4*)cnt_w,  NPAPER / 4);
    zero_kernel<<<8, ZT>>>((float4*)cnt_wb, NAUTHOR / 4);

    // ---- layer 1: scatter ----
    scatter_kernel<<<ceil_div((long long)Ec * 32, 256), 256>>>(xp, cs, cd, sum_c, cnt_c, Ec);
    scatter_kernel<<<ceil_div((long long)Ew * 32, 256), 256>>>(xa, ws, wd, sum_w, cnt_w, Ew);
    scatter_kernel<<<ceil_div((long long)Eb * 32, 256), 256>>>(xp, bs, bd, sum_wb, cnt_wb, Eb);

    inv_kernel<<<ceil_div(NPAPER, 256), 256>>>(cnt_c, NPAPER);
    inv_kernel<<<ceil_div(NPAPER, 256), 256>>>(cnt_w, NPAPER);
    inv_kernel<<<ceil_div(NAUTHOR, 256), 256>>>(cnt_wb, NAUTHOR);

    wsum_kernel<<<64, 256>>>(Wr1, Wr1 + DD * DD, wr1, DD * DD);
    wsum_kernel<<<64, 256>>>(Wr2, Wr2 + DD * DD, wr2, DD * DD);

    // ---- layer 1: tensor GEMMs (+bias, +relu) ----
    sage_gemm_mma<<<GP, 256, SMEM_TOTAL>>>(
        hp,
        sum_c, cnt_c, Wm1,
        sum_w, cnt_w, Wm1 + DD * DD,
        xp, wr1,
        b1, b1 + DD, NPAPER, 1);
    sage_gemm_mma<<<GA, 256, SMEM_TOTAL>>>(
        ha,
        sum_wb, cnt_wb, Wm1 + 2 * DD * DD,
        nullptr, nullptr, nullptr,
        xa, Wr1 + 2 * DD * DD,
        b1 + 2 * DD, nullptr, NAUTHOR, 1);

    // ---- layer 2: zero sums (counts reused) ----
    zero_kernel<<<ZB, ZT>>>((float4*)sum_c,  NPAPER * DD / 4);
    zero_kernel<<<ZB, ZT>>>((float4*)sum_w,  NPAPER * DD / 4);
    zero_kernel<<<ZB, ZT>>>((float4*)sum_wb, NAUTHOR * DD / 4);

    // ---- layer 2: scatter ----
    scatter_kernel<<<ceil_div((long long)Ec * 32, 256), 256>>>(hp, cs, cd, sum_c, nullptr, Ec);
    scatter_kernel<<<ceil_div((long long)Ew * 32, 256), 256>>>(ha, ws, wd, sum_w, nullptr, Ew);
    scatter_kernel<<<ceil_div((long long)Eb * 32, 256), 256>>>(hp, bs, bd, sum_wb, nullptr, Eb);

    // ---- layer 2: tensor GEMMs -> d_out ----
    sage_gemm_mma<<<GP, 256, SMEM_TOTAL>>>(
        out_p,
        sum_c, cnt_c, Wm2,
        sum_w, cnt_w, Wm2 + DD * DD,
        hp, wr2,
        b2, b2 + DD, NPAPER, 0);
    sage_gemm_mma<<<GA, 256, SMEM_TOTAL>>>(
        out_a,
        sum_wb, cnt_wb, Wm2 + 2 * DD * DD,
        nullptr, nullptr, nullptr,
        ha, Wr2 + 2 * DD * DD,
        b2 + 2 * DD, nullptr, NAUTHOR, 0);
}

// round 6
// speedup vs baseline: 1.4373x; 1.0760x over previous
#include <cuda_runtime.h>
#include <cuda_bf16.h>
#include <cstdint>

#define DD 128
#define NPAPER 100000
#define NAUTHOR 50000
#define EC_MAX 300000
#define EW_MAX 150000
#define EB_MAX 150000

// ---------------- scratch (device globals) -----------------------------------
__device__ float g_mean_c[(size_t)NPAPER * DD];   // cites  mean -> paper
__device__ float g_mean_w[(size_t)NPAPER * DD];   // writes mean -> paper
__device__ float g_mean_wb[(size_t)NAUTHOR * DD]; // wb     mean -> author
__device__ float g_hp[(size_t)NPAPER * DD];
__device__ float g_ha[(size_t)NAUTHOR * DD];
__device__ float g_wr1[DD * DD];
__device__ float g_wr2[DD * DD];

// CSR structures (built once per launch, reused by both layers)
__device__ int g_rp_c[NPAPER + 1];
__device__ int g_rp_w[NPAPER + 1];
__device__ int g_rp_wb[NAUTHOR + 1];
__device__ int g_ci_c[EC_MAX];
__device__ int g_ci_w[EW_MAX];
__device__ int g_ci_wb[EB_MAX];
__device__ int g_pos[NPAPER];      // fill cursors (reused sequentially per type)
__device__ int g_bsums[128];       // scan block sums (reused sequentially)

__device__ __forceinline__ uint32_t f2tf32(float x) {
    uint32_t u;
    asm("cvt.rna.tf32.f32 %0, %1;" : "=r"(u) : "f"(x));
    return u;
}

// ---------------- small utility kernels --------------------------------------
__global__ void zero_int_kernel(int* __restrict__ p, int n) {
    int i = blockIdx.x * blockDim.x + threadIdx.x;
    if (i < n) p[i] = 0;
}

__global__ void wsum_kernel(const float* __restrict__ a,
                            const float* __restrict__ b,
                            float* __restrict__ o, int n) {
    int i = blockIdx.x * blockDim.x + threadIdx.x;
    if (i < n) o[i] = a[i] + b[i];
}

// ---------------- CSR build ---------------------------------------------------
__global__ void hist_kernel(const int* __restrict__ dst, int* __restrict__ cnt, int E) {
    int i = blockIdx.x * blockDim.x + threadIdx.x;
    if (i < E) atomicAdd(&cnt[dst[i]], 1);
}

// scan1: per-block (1024 elems, 256 thr) exclusive scan of cnt -> rp, block sums out
__global__ void scan1_kernel(const int* __restrict__ cnt, int* __restrict__ rp,
                             int* __restrict__ bsums, int n) {
    __shared__ int sh[256];
    int t = threadIdx.x;
    int base = blockIdx.x * 1024 + t * 4;
    int v[4];
#pragma unroll
    for (int j = 0; j < 4; ++j) v[j] = (base + j < n) ? cnt[base + j] : 0;
    int tsum = v[0] + v[1] + v[2] + v[3];
    sh[t] = tsum;
    __syncthreads();
    for (int off = 1; off < 256; off <<= 1) {
        int x = sh[t];
        if (t >= off) x += sh[t - off];
        __syncthreads();
        sh[t] = x;
        __syncthreads();
    }
    int run = sh[t] - tsum;   // exclusive prefix of this thread's chunk
#pragma unroll
    for (int j = 0; j < 4; ++j) {
        if (base + j < n) rp[base + j] = run;
        run += v[j];
    }
    if (t == 255) bsums[blockIdx.x] = sh[255];
}

// scan2: single block, exclusive scan of block sums (nb <= 128)
__global__ void scan2_kernel(int* __restrict__ bsums, int nb) {
    __shared__ int sh[128];
    int t = threadIdx.x;
    int v = (t < nb) ? bsums[t] : 0;
    sh[t] = v;
    __syncthreads();
    for (int off = 1; off < 128; off <<= 1) {
        int x = sh[t];
        if (t >= off) x += sh[t - off];
        __syncthreads();
        sh[t] = x;
        __syncthreads();
    }
    if (t < nb) bsums[t] = sh[t] - v;
}

// scan3: rp[i] += bsums[i>>10]; rp[n] = E
__global__ void scan3_kernel(int* __restrict__ rp, const int* __restrict__ bsums,
                             int n, int E) {
    int i = blockIdx.x * blockDim.x + threadIdx.x;
    if (i < n) rp[i] += bsums[i >> 10];
    if (i == 0) rp[n] = E;
}

// fill: counting-sort edges into col-index array
__global__ void fill_kernel(const int* __restrict__ src, const int* __restrict__ dst,
                            const int* __restrict__ rp, int* __restrict__ pos,
                            int* __restrict__ ci, int E) {
    int i = blockIdx.x * blockDim.x + threadIdx.x;
    if (i < E) {
        int d = dst[i];
        int o = atomicAdd(&pos[d], 1);
        ci[rp[d] + o] = src[i];
    }
}

// ---------------- gather mean (one warp per dst row) --------------------------
__global__ void gather_kernel(const float* __restrict__ x,
                              const int* __restrict__ rp,
                              const int* __restrict__ ci,
                              float* __restrict__ out, int N) {
    int w = (int)((blockIdx.x * (size_t)blockDim.x + threadIdx.x) >> 5);
    int lane = threadIdx.x & 31;
    if (w >= N) return;
    int s0 = rp[w], s1 = rp[w + 1];
    float4 acc = make_float4(0.f, 0.f, 0.f, 0.f);
    int e = s0;
    // unroll-by-2 for MLP
    for (; e + 1 < s1; e += 2) {
        int sA = __ldg(&ci[e]);
        int sB = __ldg(&ci[e + 1]);
        float4 a = *(const float4*)(x + (size_t)sA * DD + lane * 4);
        float4 b = *(const float4*)(x + (size_t)sB * DD + lane * 4);
        acc.x += a.x + b.x; acc.y += a.y + b.y;
        acc.z += a.z + b.z; acc.w += a.w + b.w;
    }
    if (e < s1) {
        int sA = __ldg(&ci[e]);
        float4 a = *(const float4*)(x + (size_t)sA * DD + lane * 4);
        acc.x += a.x; acc.y += a.y; acc.z += a.z; acc.w += a.w;
    }
    float inv = 1.0f / (float)max(s1 - s0, 1);
    acc.x *= inv; acc.y *= inv; acc.z *= inv; acc.w *= inv;
    *(float4*)(out + (size_t)w * DD + lane * 4) = acc;
}

// ---------------- tf32 mma.sync fused 3-term SAGE GEMM -----------------------
#define A_STRIDE 132
#define W_STRIDE 136
#define SMEM_TOTAL (128 * A_STRIDE * 4 + 128 * W_STRIDE * 4)

__global__ __launch_bounds__(256, 1)
void sage_gemm_mma(
    float* __restrict__ out,
    const float* __restrict__ A0, const float* __restrict__ W0,
    const float* __restrict__ A1, const float* __restrict__ W1,
    const float* __restrict__ Ar, const float* __restrict__ Wr,
    const float* __restrict__ bias0, const float* __restrict__ bias1,
    int M, int do_relu)
{
    extern __shared__ uint32_t smem[];
    uint32_t* Asm = smem;
    uint32_t* Wsm = smem + 128 * A_STRIDE;

    const int tid = threadIdx.x;
    const int wid = tid >> 5;
    const int lane = tid & 31;
    const int group = lane >> 2;
    const int tig = lane & 3;
    const int wr = (wid & 3) * 32;
    const int wc = (wid >> 2) * 64;
    const int row0 = blockIdx.x * 128;

    float acc[2][8][4];
#pragma unroll
    for (int am = 0; am < 2; ++am)
#pragma unroll
        for (int nb = 0; nb < 8; ++nb)
#pragma unroll
            for (int j = 0; j < 4; ++j) acc[am][nb][j] = 0.f;

    const float* Aarr[3] = {A0, A1, Ar};
    const float* Warr[3] = {W0, W1, Wr};

    for (int t = 0; t < 3; ++t) {
        const float* A = Aarr[t];
        if (A == nullptr) continue;
        const float* W = Warr[t];

#pragma unroll
        for (int i = 0; i < 16; ++i) {
            int idx = tid + i * 256;
            int r = idx >> 5;
            int k4 = idx & 31;
            int gr = row0 + r;
            uint4 u = make_uint4(0u, 0u, 0u, 0u);
            if (gr < M) {
                float4 v = *(const float4*)(A + (size_t)gr * DD + k4 * 4);
                u.x = f2tf32(v.x); u.y = f2tf32(v.y);
                u.z = f2tf32(v.z); u.w = f2tf32(v.w);
            }
            *(uint4*)&Asm[r * A_STRIDE + k4 * 4] = u;
        }
#pragma unroll
        for (int i = 0; i < 16; ++i) {
            int idx = tid + i * 256;
            int k = idx >> 5;
            int n4 = idx & 31;
            float4 w = *(const float4*)(W + (size_t)k * DD + n4 * 4);
            uint4 u;
            u.x = f2tf32(w.x); u.y = f2tf32(w.y);
            u.z = f2tf32(w.z); u.w = f2tf32(w.w);
            *(uint4*)&Wsm[k * W_STRIDE + n4 * 4] = u;
        }
        __syncthreads();

#pragma unroll 4
        for (int k0 = 0; k0 < DD; k0 += 8) {
            uint32_t a[2][4];
#pragma unroll
            for (int am = 0; am < 2; ++am) {
                int rb = wr + am * 16;
                a[am][0] = Asm[(rb + group) * A_STRIDE + k0 + tig];
                a[am][1] = Asm[(rb + group + 8) * A_STRIDE + k0 + tig];
                a[am][2] = Asm[(rb + group) * A_STRIDE + k0 + tig + 4];
                a[am][3] = Asm[(rb + group + 8) * A_STRIDE + k0 + tig + 4];
            }
#pragma unroll
            for (int nb = 0; nb < 8; ++nb) {
                uint32_t b0 = Wsm[(k0 + tig) * W_STRIDE + wc + nb * 8 + group];
                uint32_t b1 = Wsm[(k0 + tig + 4) * W_STRIDE + wc + nb * 8 + group];
#pragma unroll
                for (int am = 0; am < 2; ++am) {
                    asm volatile(
                        "mma.sync.aligned.m16n8k8.row.col.f32.tf32.tf32.f32 "
                        "{%0,%1,%2,%3}, {%4,%5,%6,%7}, {%8,%9}, {%0,%1,%2,%3};"
                        : "+f"(acc[am][nb][0]), "+f"(acc[am][nb][1]),
                          "+f"(acc[am][nb][2]), "+f"(acc[am][nb][3])
                        : "r"(a[am][0]), "r"(a[am][1]), "r"(a[am][2]), "r"(a[am][3]),
                          "r"(b0), "r"(b1));
                }
            }
        }
        __syncthreads();
    }

#pragma unroll
    for (int nb = 0; nb < 8; ++nb) {
        int col = wc + nb * 8 + 2 * tig;
        float bA = 0.f, bB = 0.f;
        if (bias0 != nullptr) { bA = bias0[col]; bB = bias0[col + 1]; }
        if (bias1 != nullptr) { bA += bias1[col]; bB += bias1[col + 1]; }
#pragma unroll
        for (int am = 0; am < 2; ++am) {
            int r_lo = row0 + wr + am * 16 + group;
            int r_hi = r_lo + 8;
            float v0 = acc[am][nb][0] + bA, v1 = acc[am][nb][1] + bB;
            float v2 = acc[am][nb][2] + bA, v3 = acc[am][nb][3] + bB;
            if (do_relu) {
                v0 = fmaxf(v0, 0.f); v1 = fmaxf(v1, 0.f);
                v2 = fmaxf(v2, 0.f); v3 = fmaxf(v3, 0.f);
            }
            if (r_lo < M) *(float2*)&out[(size_t)r_lo * DD + col] = make_float2(v0, v1);
            if (r_hi < M) *(float2*)&out[(size_t)r_hi * DD + col] = make_float2(v2, v3);
        }
    }
}

// ---------------- launch ----------------------------------------------------
static inline int ceil_div(long long a, int b) { return (int)((a + b - 1) / b); }

static void build_csr(const int* src, const int* dst, int E, int N,
                      int* rp, int* ci, int* pos, int* bsums) {
    // pos doubles as histogram counter, then as fill cursor
    zero_int_kernel<<<ceil_div(N, 256), 256>>>(pos, N);
    hist_kernel<<<ceil_div(E, 256), 256>>>(dst, pos, E);
    int nb = ceil_div(N, 1024);
    scan1_kernel<<<nb, 256>>>(pos, rp, bsums, N);
    scan2_kernel<<<1, 128>>>(bsums, nb);
    scan3_kernel<<<ceil_div(N, 256), 256>>>(rp, bsums, N, E);
    zero_int_kernel<<<ceil_div(N, 256), 256>>>(pos, N);
    fill_kernel<<<ceil_div(E, 256), 256>>>(src, dst, rp, pos, ci, E);
}

extern "C" void kernel_launch(void* const* d_in, const int* in_sizes, int n_in,
                              void* d_out, int out_size)
{
    const float* xp  = (const float*)d_in[0];
    const float* xa  = (const float*)d_in[1];
    const float* Wm1 = (const float*)d_in[2];
    const float* b1  = (const float*)d_in[3];
    const float* Wr1 = (const float*)d_in[4];
    const float* Wm2 = (const float*)d_in[5];
    const float* b2  = (const float*)d_in[6];
    const float* Wr2 = (const float*)d_in[7];
    const int* cs = (const int*)d_in[8];
    const int* cd = (const int*)d_in[9];
    const int* ws = (const int*)d_in[10];
    const int* wd = (const int*)d_in[11];
    const int* bs = (const int*)d_in[12];
    const int* bd = (const int*)d_in[13];
    const int Ec = in_sizes[8];
    const int Ew = in_sizes[10];
    const int Eb = in_sizes[12];

    float *mean_c, *mean_w, *mean_wb, *hp, *ha, *wr1, *wr2;
    int *rp_c, *rp_w, *rp_wb, *ci_c, *ci_w, *ci_wb, *pos, *bsums;
    cudaGetSymbolAddress((void**)&mean_c,  g_mean_c);
    cudaGetSymbolAddress((void**)&mean_w,  g_mean_w);
    cudaGetSymbolAddress((void**)&mean_wb, g_mean_wb);
    cudaGetSymbolAddress((void**)&hp,    g_hp);
    cudaGetSymbolAddress((void**)&ha,    g_ha);
    cudaGetSymbolAddress((void**)&wr1,   g_wr1);
    cudaGetSymbolAddress((void**)&wr2,   g_wr2);
    cudaGetSymbolAddress((void**)&rp_c,  g_rp_c);
    cudaGetSymbolAddress((void**)&rp_w,  g_rp_w);
    cudaGetSymbolAddress((void**)&rp_wb, g_rp_wb);
    cudaGetSymbolAddress((void**)&ci_c,  g_ci_c);
    cudaGetSymbolAddress((void**)&ci_w,  g_ci_w);
    cudaGetSymbolAddress((void**)&ci_wb, g_ci_wb);
    cudaGetSymbolAddress((void**)&pos,   g_pos);
    cudaGetSymbolAddress((void**)&bsums, g_bsums);

    cudaFuncSetAttribute(sage_gemm_mma, cudaFuncAttributeMaxDynamicSharedMemorySize, SMEM_TOTAL);

    float* out_p = (float*)d_out;
    float* out_a = out_p + (size_t)NPAPER * DD;

    const int GP = ceil_div(NPAPER, 128);
    const int GA = ceil_div(NAUTHOR, 128);

    // ---- CSR build (once; topology shared by both layers) ----
    build_csr(cs, cd, Ec, NPAPER,  rp_c,  ci_c,  pos, bsums);
    build_csr(ws, wd, Ew, NPAPER,  rp_w,  ci_w,  pos, bsums);
    build_csr(bs, bd, Eb, NAUTHOR, rp_wb, ci_wb, pos, bsums);

    // combined root weights
    wsum_kernel<<<64, 256>>>(Wr1, Wr1 + DD * DD, wr1, DD * DD);
    wsum_kernel<<<64, 256>>>(Wr2, Wr2 + DD * DD, wr2, DD * DD);

    // ---- layer 1: gather means ----
    gather_kernel<<<ceil_div((long long)NPAPER * 32, 256), 256>>>(xp, rp_c,  ci_c,  mean_c,  NPAPER);
    gather_kernel<<<ceil_div((long long)NPAPER * 32, 256), 256>>>(xa, rp_w,  ci_w,  mean_w,  NPAPER);
    gather_kernel<<<ceil_div((long long)NAUTHOR * 32, 256), 256>>>(xp, rp_wb, ci_wb, mean_wb, NAUTHOR);

    // ---- layer 1: GEMMs (+bias, +relu) ----
    sage_gemm_mma<<<GP, 256, SMEM_TOTAL>>>(
        hp, mean_c, Wm1, mean_w, Wm1 + DD * DD, xp, wr1,
        b1, b1 + DD, NPAPER, 1);
    sage_gemm_mma<<<GA, 256, SMEM_TOTAL>>>(
        ha, mean_wb, Wm1 + 2 * DD * DD, nullptr, nullptr, xa, Wr1 + 2 * DD * DD,
        b1 + 2 * DD, nullptr, NAUTHOR, 1);

    // ---- layer 2: gather means on hidden activations ----
    gather_kernel<<<ceil_div((long long)NPAPER * 32, 256), 256>>>(hp, rp_c,  ci_c,  mean_c,  NPAPER);
    gather_kernel<<<ceil_div((long long)NPAPER * 32, 256), 256>>>(ha, rp_w,  ci_w,  mean_w,  NPAPER);
    gather_kernel<<<ceil_div((long long)NAUTHOR * 32, 256), 256>>>(hp, rp_wb, ci_wb, mean_wb, NAUTHOR);

    // ---- layer 2: GEMMs -> d_out ----
    sage_gemm_mma<<<GP, 256, SMEM_TOTAL>>>(
        out_p, mean_c, Wm2, mean_w, Wm2 + DD * DD, hp, wr2,
        b2, b2 + DD, NPAPER, 0);
    sage_gemm_mma<<<GA, 256, SMEM_TOTAL>>>(
        out_a, mean_wb, Wm2 + 2 * DD * DD, nullptr, nullptr, ha, Wr2 + 2 * DD * DD,
        b2 + 2 * DD, nullptr, NAUTHOR, 0);
}

// round 10
// speedup vs baseline: 2.9559x; 2.0565x over previous
#include <cuda_runtime.h>
#include <cuda_bf16.h>
#include <cstdint>

#define DD 128
#define NPAPER 100000
#define NAUTHOR 50000
#define EC_MAX 300000
#define EW_MAX 150000
#define EB_MAX 150000

// ---------------- scratch (device globals) -----------------------------------
__device__ float g_mean_c[(size_t)NPAPER * DD];
__device__ float g_mean_w[(size_t)NPAPER * DD];
__device__ float g_mean_wb[(size_t)NAUTHOR * DD];
__device__ float g_hp[(size_t)NPAPER * DD];
__device__ float g_ha[(size_t)NAUTHOR * DD];
__device__ float g_wsp1[384 * DD];   // stacked W, layer1 paper: [W0;W1;Wr0+Wr1]
__device__ float g_wsa1[256 * DD];   // stacked W, layer1 author: [W2;Wr2]
__device__ float g_wsp2[384 * DD];
__device__ float g_wsa2[256 * DD];

// CSR structures (built once per launch, reused by both layers)
__device__ int g_rp_c[NPAPER + 1];
__device__ int g_rp_w[NPAPER + 1];
__device__ int g_rp_wb[NAUTHOR + 1];
__device__ int g_ci_c[EC_MAX];
__device__ int g_ci_w[EW_MAX];
__device__ int g_ci_wb[EB_MAX];
__device__ int g_pos[NPAPER];
__device__ int g_bsums[128];

__device__ __forceinline__ uint32_t smem_u32(const void* p) {
    uint32_t a;
    asm("{ .reg .u64 t; cvta.to.shared.u64 t, %1; cvt.u32.u64 %0, t; }" : "=r"(a) : "l"(p));
    return a;
}
__device__ __forceinline__ uint32_t rna(uint32_t raw) {
    // round-to-nearest tf32 on raw fp32 bits (register-side, post-LDS)
    uint32_t u;
    asm("cvt.rna.tf32.f32 %0, %1;" : "=r"(u) : "f"(__uint_as_float(raw)));
    return u;
}
template <int N>
__device__ __forceinline__ void cpasync_wait() {
    asm volatile("cp.async.wait_group %0;" :: "n"(N) : "memory");
}
__device__ __forceinline__ void cpasync_commit() {
    asm volatile("cp.async.commit_group;" ::: "memory");
}
__device__ __forceinline__ void cpasync16(uint32_t dst, const void* src, int src_bytes) {
    asm volatile("cp.async.ca.shared.global [%0], [%1], 16, %2;"
                 :: "r"(dst), "l"(src), "r"(src_bytes) : "memory");
}

// ---------------- small utility kernels --------------------------------------
__global__ void zero_int_kernel(int* __restrict__ p, int n) {
    int i = blockIdx.x * blockDim.x + threadIdx.x;
    if (i < n) p[i] = 0;
}

// Build stacked weights for one layer.
__global__ void stack_kernel(const float* __restrict__ Wm, const float* __restrict__ Wr,
                             float* __restrict__ SP, float* __restrict__ SA) {
    int i = blockIdx.x * blockDim.x + threadIdx.x;
    if (i < 32768) {
        SP[i] = Wm[i];
    } else if (i < 49152) {
        int j = i - 32768;
        SP[i] = Wr[j] + Wr[16384 + j];
    } else if (i < 65536) {
        int j = i - 49152;
        SA[j] = Wm[32768 + j];
    } else if (i < 81920) {
        int j = i - 65536;
        SA[16384 + j] = Wr[32768 + j];
    }
}

// ---------------- CSR build ---------------------------------------------------
__global__ void hist_kernel(const int* __restrict__ dst, int* __restrict__ cnt, int E) {
    int i = blockIdx.x * blockDim.x + threadIdx.x;
    if (i < E) atomicAdd(&cnt[dst[i]], 1);
}

__global__ void scan1_kernel(const int* __restrict__ cnt, int* __restrict__ rp,
                             int* __restrict__ bsums, int n) {
    __shared__ int sh[256];
    int t = threadIdx.x;
    int base = blockIdx.x * 1024 + t * 4;
    int v[4];
#pragma unroll
    for (int j = 0; j < 4; ++j) v[j] = (base + j < n) ? cnt[base + j] : 0;
    int tsum = v[0] + v[1] + v[2] + v[3];
    sh[t] = tsum;
    __syncthreads();
    for (int off = 1; off < 256; off <<= 1) {
        int x = sh[t];
        if (t >= off) x += sh[t - off];
        __syncthreads();
        sh[t] = x;
        __syncthreads();
    }
    int run = sh[t] - tsum;
#pragma unroll
    for (int j = 0; j < 4; ++j) {
        if (base + j < n) rp[base + j] = run;
        run += v[j];
    }
    if (t == 255) bsums[blockIdx.x] = sh[255];
}

__global__ void scan2_kernel(int* __restrict__ bsums, int nb) {
    __shared__ int sh[128];
    int t = threadIdx.x;
    int v = (t < nb) ? bsums[t] : 0;
    sh[t] = v;
    __syncthreads();
    for (int off = 1; off < 128; off <<= 1) {
        int x = sh[t];
        if (t >= off) x += sh[t - off];
        __syncthreads();
        sh[t] = x;
        __syncthreads();
    }
    if (t < nb) bsums[t] = sh[t] - v;
}

__global__ void scan3_kernel(int* __restrict__ rp, const int* __restrict__ bsums,
                             int n, int E) {
    int i = blockIdx.x * blockDim.x + threadIdx.x;
    if (i < n) rp[i] += bsums[i >> 10];
    if (i == 0) rp[n] = E;
}

__global__ void fill_kernel(const int* __restrict__ src, const int* __restrict__ dst,
                            const int* __restrict__ rp, int* __restrict__ pos,
                            int* __restrict__ ci, int E) {
    int i = blockIdx.x * blockDim.x + threadIdx.x;
    if (i < E) {
        int d = dst[i];
        int o = atomicAdd(&pos[d], 1);
        ci[rp[d] + o] = src[i];
    }
}

// ---------------- gather mean (one warp per dst row) --------------------------
__global__ void gather_kernel(const float* __restrict__ x,
                              const int* __restrict__ rp,
                              const int* __restrict__ ci,
                              float* __restrict__ out, int N) {
    int w = (int)((blockIdx.x * (size_t)blockDim.x + threadIdx.x) >> 5);
    int lane = threadIdx.x & 31;
    if (w >= N) return;
    int s0 = rp[w], s1 = rp[w + 1];
    float4 acc = make_float4(0.f, 0.f, 0.f, 0.f);
    int e = s0;
    for (; e + 1 < s1; e += 2) {
        int sA = __ldg(&ci[e]);
        int sB = __ldg(&ci[e + 1]);
        float4 a = *(const float4*)(x + (size_t)sA * DD + lane * 4);
        float4 b = *(const float4*)(x + (size_t)sB * DD + lane * 4);
        acc.x += a.x + b.x; acc.y += a.y + b.y;
        acc.z += a.z + b.z; acc.w += a.w + b.w;
    }
    if (e < s1) {
        int sA = __ldg(&ci[e]);
        float4 a = *(const float4*)(x + (size_t)sA * DD + lane * 4);
        acc.x += a.x; acc.y += a.y; acc.z += a.z; acc.w += a.w;
    }
    float inv = 1.0f / (float)max(s1 - s0, 1);
    acc.x *= inv; acc.y *= inv; acc.z *= inv; acc.w *= inv;
    *(float4*)(out + (size_t)w * DD + lane * 4) = acc;
}

// ---------------- pipelined tf32 GEMM over stacked K --------------------------
// out[M,128] = concat_k(A_t) @ Wstack + bias, A selected per 128-K segment.
// BM=128, BN=128, BK=32; cp.async double-buffered; RNA tf32 rounding applied
// on fragments in registers (post-LDS) to keep cp.async raw staging.
#define AS 36
#define WS 136
#define STG (128 * AS + 32 * WS)
#define GEMM_SMEM (2 * STG * 4)

__global__ __launch_bounds__(256, 1)
void sage_gemm_pipe(
    float* __restrict__ out,
    const float* __restrict__ A0, const float* __restrict__ A1,
    const float* __restrict__ A2,
    const float* __restrict__ Wstack,
    const float* __restrict__ bias0, const float* __restrict__ bias1,
    int M, int K, int do_relu)
{
    extern __shared__ uint32_t smem[];
    const uint32_t sbase = smem_u32(smem);

    const int tid = threadIdx.x;
    const int wid = tid >> 5;
    const int lane = tid & 31;
    const int group = lane >> 2;
    const int tig = lane & 3;
    const int wr = (wid & 3) * 32;
    const int wc = (wid >> 2) * 64;
    const int row0 = blockIdx.x * 128;
    const int nkt = K >> 5;

    const float* Aarr[3] = {A0, A1, A2};

    float acc[2][8][4];
#pragma unroll
    for (int am = 0; am < 2; ++am)
#pragma unroll
        for (int nb = 0; nb < 8; ++nb)
#pragma unroll
            for (int j = 0; j < 4; ++j) acc[am][nb][j] = 0.f;

    auto issue = [&](int kt) {
        int s = kt & 1;
        uint32_t abase = sbase + (uint32_t)(s * STG) * 4u;
        uint32_t wbase = abase + 128u * AS * 4u;
        const float* A = Aarr[kt >> 2];
        int kin = (kt & 3) * 32;
#pragma unroll
        for (int i = 0; i < 4; ++i) {
            int idx = tid + i * 256;
            int r = idx >> 3;
            int c4 = idx & 7;
            int gr = row0 + r;
            const float* src = A + (size_t)gr * DD + kin + c4 * 4;
            cpasync16(abase + (uint32_t)(r * AS + c4 * 4) * 4u, src, gr < M ? 16 : 0);
        }
        const float* Wk = Wstack + (size_t)(kt * 32) * DD;
#pragma unroll
        for (int i = 0; i < 4; ++i) {
            int idx = tid + i * 256;
            int k = idx >> 5;
            int n4 = idx & 31;
            cpasync16(wbase + (uint32_t)(k * WS + n4 * 4) * 4u,
                      Wk + (size_t)k * DD + n4 * 4, 16);
        }
        cpasync_commit();
    };

    issue(0);
    for (int kt = 0; kt < nkt; ++kt) {
        if (kt + 1 < nkt) {
            issue(kt + 1);
            cpasync_wait<1>();
        } else {
            cpasync_wait<0>();
        }
        __syncthreads();

        const uint32_t* As = smem + (kt & 1) * STG;
        const uint32_t* Ws = As + 128 * AS;

#pragma unroll
        for (int k0 = 0; k0 < 32; k0 += 8) {
            uint32_t a[2][4];
#pragma unroll
            for (int am = 0; am < 2; ++am) {
                int rb = wr + am * 16;
                a[am][0] = rna(As[(rb + group) * AS + k0 + tig]);
                a[am][1] = rna(As[(rb + group + 8) * AS + k0 + tig]);
                a[am][2] = rna(As[(rb + group) * AS + k0 + tig + 4]);
                a[am][3] = rna(As[(rb + group + 8) * AS + k0 + tig + 4]);
            }
#pragma unroll
            for (int nb = 0; nb < 8; ++nb) {
                uint32_t b0 = rna(Ws[(k0 + tig) * WS + wc + nb * 8 + group]);
                uint32_t b1 = rna(Ws[(k0 + tig + 4) * WS + wc + nb * 8 + group]);
#pragma unroll
                for (int am = 0; am < 2; ++am) {
                    asm volatile(
                        "mma.sync.aligned.m16n8k8.row.col.f32.tf32.tf32.f32 "
                        "{%0,%1,%2,%3}, {%4,%5,%6,%7}, {%8,%9}, {%0,%1,%2,%3};"
                        : "+f"(acc[am][nb][0]), "+f"(acc[am][nb][1]),
                          "+f"(acc[am][nb][2]), "+f"(acc[am][nb][3])
                        : "r"(a[am][0]), "r"(a[am][1]), "r"(a[am][2]), "r"(a[am][3]),
                          "r"(b0), "r"(b1));
                }
            }
        }
        __syncthreads();
    }

    // --- epilogue ---
#pragma unroll
    for (int nb = 0; nb < 8; ++nb) {
        int col = wc + nb * 8 + 2 * tig;
        float bA = 0.f, bB = 0.f;
        if (bias0 != nullptr) { bA = bias0[col]; bB = bias0[col + 1]; }
        if (bias1 != nullptr) { bA += bias1[col]; bB += bias1[col + 1]; }
#pragma unroll
        for (int am = 0; am < 2; ++am) {
            int r_lo = row0 + wr + am * 16 + group;
            int r_hi = r_lo + 8;
            float v0 = acc[am][nb][0] + bA, v1 = acc[am][nb][1] + bB;
            float v2 = acc[am][nb][2] + bA, v3 = acc[am][nb][3] + bB;
            if (do_relu) {
                v0 = fmaxf(v0, 0.f); v1 = fmaxf(v1, 0.f);
                v2 = fmaxf(v2, 0.f); v3 = fmaxf(v3, 0.f);
            }
            if (r_lo < M) *(float2*)&out[(size_t)r_lo * DD + col] = make_float2(v0, v1);
            if (r_hi < M) *(float2*)&out[(size_t)r_hi * DD + col] = make_float2(v2, v3);
        }
    }
}

// ---------------- launch ----------------------------------------------------
static inline int ceil_div(long long a, int b) { return (int)((a + b - 1) / b); }

static void build_csr(const int* src, const int* dst, int E, int N,
                      int* rp, int* ci, int* pos, int* bsums) {
    zero_int_kernel<<<ceil_div(N, 256), 256>>>(pos, N);
    hist_kernel<<<ceil_div(E, 256), 256>>>(dst, pos, E);
    int nb = ceil_div(N, 1024);
    scan1_kernel<<<nb, 256>>>(pos, rp, bsums, N);
    scan2_kernel<<<1, 128>>>(bsums, nb);
    scan3_kernel<<<ceil_div(N, 256), 256>>>(rp, bsums, N, E);
    zero_int_kernel<<<ceil_div(N, 256), 256>>>(pos, N);
    fill_kernel<<<ceil_div(E, 256), 256>>>(src, dst, rp, pos, ci, E);
}

extern "C" void kernel_launch(void* const* d_in, const int* in_sizes, int n_in,
                              void* d_out, int out_size)
{
    const float* xp  = (const float*)d_in[0];
    const float* xa  = (const float*)d_in[1];
    const float* Wm1 = (const float*)d_in[2];
    const float* b1  = (const float*)d_in[3];
    const float* Wr1 = (const float*)d_in[4];
    const float* Wm2 = (const float*)d_in[5];
    const float* b2  = (const float*)d_in[6];
    const float* Wr2 = (const float*)d_in[7];
    const int* cs = (const int*)d_in[8];
    const int* cd = (const int*)d_in[9];
    const int* ws = (const int*)d_in[10];
    const int* wd = (const int*)d_in[11];
    const int* bs = (const int*)d_in[12];
    const int* bd = (const int*)d_in[13];
    const int Ec = in_sizes[8];
    const int Ew = in_sizes[10];
    const int Eb = in_sizes[12];

    float *mean_c, *mean_w, *mean_wb, *hp, *ha, *wsp1, *wsa1, *wsp2, *wsa2;
    int *rp_c, *rp_w, *rp_wb, *ci_c, *ci_w, *ci_wb, *pos, *bsums;
    cudaGetSymbolAddress((void**)&mean_c,  g_mean_c);
    cudaGetSymbolAddress((void**)&mean_w,  g_mean_w);
    cudaGetSymbolAddress((void**)&mean_wb, g_mean_wb);
    cudaGetSymbolAddress((void**)&hp,    g_hp);
    cudaGetSymbolAddress((void**)&ha,    g_ha);
    cudaGetSymbolAddress((void**)&wsp1,  g_wsp1);
    cudaGetSymbolAddress((void**)&wsa1,  g_wsa1);
    cudaGetSymbolAddress((void**)&wsp2,  g_wsp2);
    cudaGetSymbolAddress((void**)&wsa2,  g_wsa2);
    cudaGetSymbolAddress((void**)&rp_c,  g_rp_c);
    cudaGetSymbolAddress((void**)&rp_w,  g_rp_w);
    cudaGetSymbolAddress((void**)&rp_wb, g_rp_wb);
    cudaGetSymbolAddress((void**)&ci_c,  g_ci_c);
    cudaGetSymbolAddress((void**)&ci_w,  g_ci_w);
    cudaGetSymbolAddress((void**)&ci_wb, g_ci_wb);
    cudaGetSymbolAddress((void**)&pos,   g_pos);
    cudaGetSymbolAddress((void**)&bsums, g_bsums);

    cudaFuncSetAttribute(sage_gemm_pipe, cudaFuncAttributeMaxDynamicSharedMemorySize, GEMM_SMEM);

    float* out_p = (float*)d_out;
    float* out_a = out_p + (size_t)NPAPER * DD;

    const int GP = ceil_div(NPAPER, 128);
    const int GA = ceil_div(NAUTHOR, 128);

    // ---- CSR build (topology shared by both layers) ----
    build_csr(cs, cd, Ec, NPAPER,  rp_c,  ci_c,  pos, bsums);
    build_csr(ws, wd, Ew, NPAPER,  rp_w,  ci_w,  pos, bsums);
    build_csr(bs, bd, Eb, NAUTHOR, rp_wb, ci_wb, pos, bsums);

    // ---- stacked weights ----
    stack_kernel<<<320, 256>>>(Wm1, Wr1, wsp1, wsa1);
    stack_kernel<<<320, 256>>>(Wm2, Wr2, wsp2, wsa2);

    // ---- layer 1: gather means ----
    gather_kernel<<<ceil_div((long long)NPAPER * 32, 256), 256>>>(xp, rp_c,  ci_c,  mean_c,  NPAPER);
    gather_kernel<<<ceil_div((long long)NPAPER * 32, 256), 256>>>(xa, rp_w,  ci_w,  mean_w,  NPAPER);
    gather_kernel<<<ceil_div((long long)NAUTHOR * 32, 256), 256>>>(xp, rp_wb, ci_wb, mean_wb, NAUTHOR);

    // ---- layer 1: GEMMs (+bias, +relu) ----
    sage_gemm_pipe<<<GP, 256, GEMM_SMEM>>>(
        hp, mean_c, mean_w, xp, wsp1, b1, b1 + DD, NPAPER, 384, 1);
    sage_gemm_pipe<<<GA, 256, GEMM_SMEM>>>(
        ha, mean_wb, xa, nullptr, wsa1, b1 + 2 * DD, nullptr, NAUTHOR, 256, 1);

    // ---- layer 2: gather means on hidden activations ----
    gather_kernel<<<ceil_div((long long)NPAPER * 32, 256), 256>>>(hp, rp_c,  ci_c,  mean_c,  NPAPER);
    gather_kernel<<<ceil_div((long long)NPAPER * 32, 256), 256>>>(ha, rp_w,  ci_w,  mean_w,  NPAPER);
    gather_kernel<<<ceil_div((long long)NAUTHOR * 32, 256), 256>>>(hp, rp_wb, ci_wb, mean_wb, NAUTHOR);

    // ---- layer 2: GEMMs -> d_out ----
    sage_gemm_pipe<<<GP, 256, GEMM_SMEM>>>(
        out_p, mean_c, mean_w, hp, wsp2, b2, b2 + DD, NPAPER, 384, 0);
    sage_gemm_pipe<<<GA, 256, GEMM_SMEM>>>(
        out_a, mean_wb, ha, nullptr, wsa2, b2 + 2 * DD, nullptr, NAUTHOR, 256, 0);
}

// round 11
// speedup vs baseline: 3.5981x; 1.2173x over previous
#include <cuda_runtime.h>
#include <cuda_bf16.h>
#include <cstdint>

#define DD 128
#define NPAPER 100000
#define NAUTHOR 50000
#define NTOT 250000              // paper-cites + paper-writes + author-wb rows
#define ETOT_MAX 600000

// ---------------- scratch (device globals) -----------------------------------
__device__ float g_mean_c[(size_t)NPAPER * DD];
__device__ float g_mean_w[(size_t)NPAPER * DD];
__device__ float g_mean_wb[(size_t)NAUTHOR * DD];
__device__ float g_hp[(size_t)NPAPER * DD];
__device__ float g_ha[(size_t)NAUTHOR * DD];
__device__ float g_wsp1[384 * DD];
__device__ float g_wsa1[256 * DD];
__device__ float g_wsp2[384 * DD];
__device__ float g_wsa2[256 * DD];

// unified CSR over all 3 edge types (built once, reused by both layers)
__device__ int g_rp[NTOT + 1];
__device__ int g_ci[ETOT_MAX];
__device__ int g_pos[NTOT];
__device__ int g_bsums[256];

__device__ __forceinline__ uint32_t smem_u32(const void* p) {
    uint32_t a;
    asm("{ .reg .u64 t; cvta.to.shared.u64 t, %1; cvt.u32.u64 %0, t; }" : "=r"(a) : "l"(p));
    return a;
}
__device__ __forceinline__ uint32_t rna(uint32_t raw) {
    uint32_t u;
    asm("cvt.rna.tf32.f32 %0, %1;" : "=r"(u) : "f"(__uint_as_float(raw)));
    return u;
}
template <int N>
__device__ __forceinline__ void cpasync_wait() {
    asm volatile("cp.async.wait_group %0;" :: "n"(N) : "memory");
}
__device__ __forceinline__ void cpasync_commit() {
    asm volatile("cp.async.commit_group;" ::: "memory");
}
__device__ __forceinline__ void cpasync16(uint32_t dst, const void* src, int src_bytes) {
    asm volatile("cp.async.ca.shared.global [%0], [%1], 16, %2;"
                 :: "r"(dst), "l"(src), "r"(src_bytes) : "memory");
}

// ---------------- small utility kernels --------------------------------------
__global__ void zero_int_kernel(int* __restrict__ p, int n) {
    int i = blockIdx.x * blockDim.x + threadIdx.x;
    if (i < n) p[i] = 0;
}

__global__ void stack_kernel(const float* __restrict__ Wm, const float* __restrict__ Wr,
                             float* __restrict__ SP, float* __restrict__ SA) {
    int i = blockIdx.x * blockDim.x + threadIdx.x;
    if (i < 32768) {
        SP[i] = Wm[i];
    } else if (i < 49152) {
        int j = i - 32768;
        SP[i] = Wr[j] + Wr[16384 + j];
    } else if (i < 65536) {
        int j = i - 49152;
        SA[j] = Wm[32768 + j];
    } else if (i < 81920) {
        int j = i - 65536;
        SA[16384 + j] = Wr[32768 + j];
    }
}

// ---------------- unified CSR build ------------------------------------------
// node id space: cites-dst d -> d; writes-dst d -> 100000+d; wb-dst d -> 200000+d
__global__ void hist3_kernel(const int* __restrict__ cd, const int* __restrict__ wd,
                             const int* __restrict__ bd, int* __restrict__ cnt,
                             int Ec, int Ew, int Eb) {
    int i = blockIdx.x * blockDim.x + threadIdx.x;
    int Etot = Ec + Ew + Eb;
    if (i >= Etot) return;
    int node;
    if (i < Ec)            node = cd[i];
    else if (i < Ec + Ew)  node = NPAPER + wd[i - Ec];
    else                   node = 2 * NPAPER + bd[i - Ec - Ew];
    atomicAdd(&cnt[node], 1);
}

__global__ void scan1_kernel(const int* __restrict__ cnt, int* __restrict__ rp,
                             int* __restrict__ bsums, int n) {
    __shared__ int sh[256];
    int t = threadIdx.x;
    int base = blockIdx.x * 1024 + t * 4;
    int v[4];
#pragma unroll
    for (int j = 0; j < 4; ++j) v[j] = (base + j < n) ? cnt[base + j] : 0;
    int tsum = v[0] + v[1] + v[2] + v[3];
    sh[t] = tsum;
    __syncthreads();
    for (int off = 1; off < 256; off <<= 1) {
        int x = sh[t];
        if (t >= off) x += sh[t - off];
        __syncthreads();
        sh[t] = x;
        __syncthreads();
    }
    int run = sh[t] - tsum;
#pragma unroll
    for (int j = 0; j < 4; ++j) {
        if (base + j < n) rp[base + j] = run;
        run += v[j];
    }
    if (t == 255) bsums[blockIdx.x] = sh[255];
}

__global__ void scan2_kernel(int* __restrict__ bsums, int nb) {
    __shared__ int sh[256];
    int t = threadIdx.x;
    int v = (t < nb) ? bsums[t] : 0;
    sh[t] = v;
    __syncthreads();
    for (int off = 1; off < 256; off <<= 1) {
        int x = sh[t];
        if (t >= off) x += sh[t - off];
        __syncthreads();
        sh[t] = x;
        __syncthreads();
    }
    if (t < nb) bsums[t] = sh[t] - v;
}

__global__ void scan3_kernel(int* __restrict__ rp, const int* __restrict__ bsums,
                             int n, int E) {
    int i = blockIdx.x * blockDim.x + threadIdx.x;
    if (i < n) rp[i] += bsums[i >> 10];
    if (i == 0) rp[n] = E;
}

__global__ void fill3_kernel(const int* __restrict__ cs, const int* __restrict__ cd,
                             const int* __restrict__ ws, const int* __restrict__ wd,
                             const int* __restrict__ bs, const int* __restrict__ bd,
                             const int* __restrict__ rp, int* __restrict__ pos,
                             int* __restrict__ ci, int Ec, int Ew, int Eb) {
    int i = blockIdx.x * blockDim.x + threadIdx.x;
    int Etot = Ec + Ew + Eb;
    if (i >= Etot) return;
    int node, s;
    if (i < Ec)           { node = cd[i];                       s = cs[i]; }
    else if (i < Ec + Ew) { node = NPAPER + wd[i - Ec];         s = ws[i - Ec]; }
    else                  { node = 2 * NPAPER + bd[i - Ec - Ew]; s = bs[i - Ec - Ew]; }
    int o = atomicAdd(&pos[node], 1);
    ci[rp[node] + o] = s;
}

// ---------------- merged gather: all 3 mean tensors, one launch ---------------
// warp w: [0,100k) -> mean_c from xP; [100k,200k) -> mean_w from xA;
//         [200k,250k) -> mean_wb from xP.
__global__ void gather3_kernel(const float* __restrict__ xP,
                               const float* __restrict__ xA,
                               const int* __restrict__ rp,
                               const int* __restrict__ ci,
                               float* __restrict__ mc,
                               float* __restrict__ mw,
                               float* __restrict__ mwb) {
    int w = (int)((blockIdx.x * (size_t)blockDim.x + threadIdx.x) >> 5);
    int lane = threadIdx.x & 31;
    if (w >= NTOT) return;
    const float* x;
    float* out;
    if (w < NPAPER)            { x = xP; out = mc  + (size_t)w * DD; }
    else if (w < 2 * NPAPER)   { x = xA; out = mw  + (size_t)(w - NPAPER) * DD; }
    else                       { x = xP; out = mwb + (size_t)(w - 2 * NPAPER) * DD; }

    int s0 = rp[w], s1 = rp[w + 1];
    float4 acc = make_float4(0.f, 0.f, 0.f, 0.f);
    int e = s0;
    for (; e + 1 < s1; e += 2) {
        int sA = __ldg(&ci[e]);
        int sB = __ldg(&ci[e + 1]);
        float4 a = *(const float4*)(x + (size_t)sA * DD + lane * 4);
        float4 b = *(const float4*)(x + (size_t)sB * DD + lane * 4);
        acc.x += a.x + b.x; acc.y += a.y + b.y;
        acc.z += a.z + b.z; acc.w += a.w + b.w;
    }
    if (e < s1) {
        int sA = __ldg(&ci[e]);
        float4 a = *(const float4*)(x + (size_t)sA * DD + lane * 4);
        acc.x += a.x; acc.y += a.y; acc.z += a.z; acc.w += a.w;
    }
    float inv = 1.0f / (float)max(s1 - s0, 1);
    acc.x *= inv; acc.y *= inv; acc.z *= inv; acc.w *= inv;
    *(float4*)(out + lane * 4) = acc;
}

// ---------------- pipelined tf32 GEMM, paper+author fused in one grid ---------
#define AS 36
#define WS 136
#define STG (128 * AS + 32 * WS)
#define GEMM_SMEM (2 * STG * 4)
#define GP_BLOCKS 782   // ceil(100000/128)
#define GA_BLOCKS 391   // ceil(50000/128)

__global__ __launch_bounds__(256, 2)
void sage_gemm_dual(
    float* __restrict__ outP, const float* __restrict__ P0,
    const float* __restrict__ P1, const float* __restrict__ P2,
    const float* __restrict__ WP, const float* __restrict__ bP0,
    const float* __restrict__ bP1,
    float* __restrict__ outA, const float* __restrict__ Q0,
    const float* __restrict__ Q1, const float* __restrict__ WA,
    const float* __restrict__ bA0,
    int do_relu)
{
    extern __shared__ uint32_t smem[];
    const uint32_t sbase = smem_u32(smem);

    const int tid = threadIdx.x;
    const int wid = tid >> 5;
    const int lane = tid & 31;
    const int group = lane >> 2;
    const int tig = lane & 3;
    const int wr = (wid & 3) * 32;
    const int wc = (wid >> 2) * 64;

    const int is_author = (blockIdx.x >= GP_BLOCKS);
    const int brow = is_author ? (blockIdx.x - GP_BLOCKS) : blockIdx.x;
    const int row0 = brow * 128;
    const int M = is_author ? NAUTHOR : NPAPER;
    const int nkt = is_author ? 8 : 12;

    const float* Aarr[3];
    const float* Wstack;
    const float* bias0;
    const float* bias1;
    float* out;
    if (is_author) {
        Aarr[0] = Q0; Aarr[1] = Q1; Aarr[2] = nullptr;
        Wstack = WA; bias0 = bA0; bias1 = nullptr; out = outA;
    } else {
        Aarr[0] = P0; Aarr[1] = P1; Aarr[2] = P2;
        Wstack = WP; bias0 = bP0; bias1 = bP1; out = outP;
    }

    float acc[2][8][4];
#pragma unroll
    for (int am = 0; am < 2; ++am)
#pragma unroll
        for (int nb = 0; nb < 8; ++nb)
#pragma unroll
            for (int j = 0; j < 4; ++j) acc[am][nb][j] = 0.f;

    auto issue = [&](int kt) {
        int s = kt & 1;
        uint32_t abase = sbase + (uint32_t)(s * STG) * 4u;
        uint32_t wbase = abase + 128u * AS * 4u;
        const float* A = Aarr[kt >> 2];
        int kin = (kt & 3) * 32;
#pragma unroll
        for (int i = 0; i < 4; ++i) {
            int idx = tid + i * 256;
            int r = idx >> 3;
            int c4 = idx & 7;
            int gr = row0 + r;
            const float* src = A + (size_t)gr * DD + kin + c4 * 4;
            cpasync16(abase + (uint32_t)(r * AS + c4 * 4) * 4u, src, gr < M ? 16 : 0);
        }
        const float* Wk = Wstack + (size_t)(kt * 32) * DD;
#pragma unroll
        for (int i = 0; i < 4; ++i) {
            int idx = tid + i * 256;
            int k = idx >> 5;
            int n4 = idx & 31;
            cpasync16(wbase + (uint32_t)(k * WS + n4 * 4) * 4u,
                      Wk + (size_t)k * DD + n4 * 4, 16);
        }
        cpasync_commit();
    };

    issue(0);
    for (int kt = 0; kt < nkt; ++kt) {
        if (kt + 1 < nkt) {
            issue(kt + 1);
            cpasync_wait<1>();
        } else {
            cpasync_wait<0>();
        }
        __syncthreads();

        const uint32_t* As = smem + (kt & 1) * STG;
        const uint32_t* Ws = As + 128 * AS;

#pragma unroll
        for (int k0 = 0; k0 < 32; k0 += 8) {
            uint32_t a[2][4];
#pragma unroll
            for (int am = 0; am < 2; ++am) {
                int rb = wr + am * 16;
                a[am][0] = rna(As[(rb + group) * AS + k0 + tig]);
                a[am][1] = rna(As[(rb + group + 8) * AS + k0 + tig]);
                a[am][2] = rna(As[(rb + group) * AS + k0 + tig + 4]);
                a[am][3] = rna(As[(rb + group + 8) * AS + k0 + tig + 4]);
            }
#pragma unroll
            for (int nb = 0; nb < 8; ++nb) {
                uint32_t b0 = rna(Ws[(k0 + tig) * WS + wc + nb * 8 + group]);
                uint32_t b1 = rna(Ws[(k0 + tig + 4) * WS + wc + nb * 8 + group]);
#pragma unroll
                for (int am = 0; am < 2; ++am) {
                    asm volatile(
                        "mma.sync.aligned.m16n8k8.row.col.f32.tf32.tf32.f32 "
                        "{%0,%1,%2,%3}, {%4,%5,%6,%7}, {%8,%9}, {%0,%1,%2,%3};"
                        : "+f"(acc[am][nb][0]), "+f"(acc[am][nb][1]),
                          "+f"(acc[am][nb][2]), "+f"(acc[am][nb][3])
                        : "r"(a[am][0]), "r"(a[am][1]), "r"(a[am][2]), "r"(a[am][3]),
                          "r"(b0), "r"(b1));
                }
            }
        }
        __syncthreads();
    }

#pragma unroll
    for (int nb = 0; nb < 8; ++nb) {
        int col = wc + nb * 8 + 2 * tig;
        float bA = 0.f, bB = 0.f;
        if (bias0 != nullptr) { bA = bias0[col]; bB = bias0[col + 1]; }
        if (bias1 != nullptr) { bA += bias1[col]; bB += bias1[col + 1]; }
#pragma unroll
        for (int am = 0; am < 2; ++am) {
            int r_lo = row0 + wr + am * 16 + group;
            int r_hi = r_lo + 8;
            float v0 = acc[am][nb][0] + bA, v1 = acc[am][nb][1] + bB;
            float v2 = acc[am][nb][2] + bA, v3 = acc[am][nb][3] + bB;
            if (do_relu) {
                v0 = fmaxf(v0, 0.f); v1 = fmaxf(v1, 0.f);
                v2 = fmaxf(v2, 0.f); v3 = fmaxf(v3, 0.f);
            }
            if (r_lo < M) *(float2*)&out[(size_t)r_lo * DD + col] = make_float2(v0, v1);
            if (r_hi < M) *(float2*)&out[(size_t)r_hi * DD + col] = make_float2(v2, v3);
        }
    }
}

// ---------------- launch ----------------------------------------------------
static inline int ceil_div(long long a, int b) { return (int)((a + b - 1) / b); }

extern "C" void kernel_launch(void* const* d_in, const int* in_sizes, int n_in,
                              void* d_out, int out_size)
{
    const float* xp  = (const float*)d_in[0];
    const float* xa  = (const float*)d_in[1];
    const float* Wm1 = (const float*)d_in[2];
    const float* b1  = (const float*)d_in[3];
    const float* Wr1 = (const float*)d_in[4];
    const float* Wm2 = (const float*)d_in[5];
    const float* b2  = (const float*)d_in[6];
    const float* Wr2 = (const float*)d_in[7];
    const int* cs = (const int*)d_in[8];
    const int* cd = (const int*)d_in[9];
    const int* ws = (const int*)d_in[10];
    const int* wd = (const int*)d_in[11];
    const int* bs = (const int*)d_in[12];
    const int* bd = (const int*)d_in[13];
    const int Ec = in_sizes[8];
    const int Ew = in_sizes[10];
    const int Eb = in_sizes[12];
    const int Etot = Ec + Ew + Eb;

    float *mean_c, *mean_w, *mean_wb, *hp, *ha, *wsp1, *wsa1, *wsp2, *wsa2;
    int *rp, *ci, *pos, *bsums;
    cudaGetSymbolAddress((void**)&mean_c,  g_mean_c);
    cudaGetSymbolAddress((void**)&mean_w,  g_mean_w);
    cudaGetSymbolAddress((void**)&mean_wb, g_mean_wb);
    cudaGetSymbolAddress((void**)&hp,    g_hp);
    cudaGetSymbolAddress((void**)&ha,    g_ha);
    cudaGetSymbolAddress((void**)&wsp1,  g_wsp1);
    cudaGetSymbolAddress((void**)&wsa1,  g_wsa1);
    cudaGetSymbolAddress((void**)&wsp2,  g_wsp2);
    cudaGetSymbolAddress((void**)&wsa2,  g_wsa2);
    cudaGetSymbolAddress((void**)&rp,    g_rp);
    cudaGetSymbolAddress((void**)&ci,    g_ci);
    cudaGetSymbolAddress((void**)&pos,   g_pos);
    cudaGetSymbolAddress((void**)&bsums, g_bsums);

    cudaFuncSetAttribute(sage_gemm_dual, cudaFuncAttributeMaxDynamicSharedMemorySize, GEMM_SMEM);

    float* out_p = (float*)d_out;
    float* out_a = out_p + (size_t)NPAPER * DD;

    // ---- unified CSR build (7 launches) ----
    zero_int_kernel<<<ceil_div(NTOT, 256), 256>>>(pos, NTOT);
    hist3_kernel<<<ceil_div(Etot, 256), 256>>>(cd, wd, bd, pos, Ec, Ew, Eb);
    int nb = ceil_div(NTOT, 1024);   // 245 <= 256
    scan1_kernel<<<nb, 256>>>(pos, rp, bsums, NTOT);
    scan2_kernel<<<1, 256>>>(bsums, nb);
    scan3_kernel<<<ceil_div(NTOT, 256), 256>>>(rp, bsums, NTOT, Etot);
    zero_int_kernel<<<ceil_div(NTOT, 256), 256>>>(pos, NTOT);
    fill3_kernel<<<ceil_div(Etot, 256), 256>>>(cs, cd, ws, wd, bs, bd, rp, pos, ci,
                                               Ec, Ew, Eb);

    // ---- stacked weights ----
    stack_kernel<<<320, 256>>>(Wm1, Wr1, wsp1, wsa1);
    stack_kernel<<<320, 256>>>(Wm2, Wr2, wsp2, wsa2);

    const int GGRID = ceil_div((long long)NTOT * 32, 256);

    // ---- layer 1 ----
    gather3_kernel<<<GGRID, 256>>>(xp, xa, rp, ci, mean_c, mean_w, mean_wb);
    sage_gemm_dual<<<GP_BLOCKS + GA_BLOCKS, 256, GEMM_SMEM>>>(
        hp, mean_c, mean_w, xp, wsp1, b1, b1 + DD,
        ha, mean_wb, xa, wsa1, b1 + 2 * DD, 1);

    // ---- layer 2 ----
    gather3_kernel<<<GGRID, 256>>>(hp, ha, rp, ci, mean_c, mean_w, mean_wb);
    sage_gemm_dual<<<GP_BLOCKS + GA_BLOCKS, 256, GEMM_SMEM>>>(
        out_p, mean_c, mean_w, hp, wsp2, b2, b2 + DD,
        out_a, mean_wb, ha, wsa2, b2 + 2 * DD, 0);
}